// round 5
// baseline (speedup 1.0000x reference)
#include <cuda_runtime.h>
#include <math.h>

// RRN sudoku. B=16, N=64, DEG=17, H=96, 32 steps.
// Round 5: fused step kernel, 192 threads/CTA (column x row-half split),
// stride-24 transposed Z tiles with LDS.128, __launch_bounds__(192,7).

#define NSTEP 32
#define RS 24            // Z tile row stride (floats): rows 0..16 real, 17..23 pad
typedef unsigned long long ull;

// ---------- device scratch (allocation-free) ----------
__device__ float g_P[2][1024 * 96];
__device__ float g_Q[1024 * 96];
__device__ float g_Ghh[1024 * 384];
__device__ float g_Xc[1024 * 384];
__device__ float g_s[1024 * 96];
__device__ float g_nodeloss[NSTEP * 1024];
__device__ int   g_nodeok[NSTEP * 1024];

// ---------- packed f32x2 helpers ----------
__device__ __forceinline__ ull pack2(float x, float y) {
    ull r; asm("mov.b64 %0,{%1,%2};" : "=l"(r) : "f"(x), "f"(y)); return r;
}
__device__ __forceinline__ void unpack2(ull v, float& x, float& y) {
    asm("mov.b64 {%0,%1},%2;" : "=f"(x), "=f"(y) : "l"(v));
}
__device__ __forceinline__ void fma2(ull& d, ull a, ull b) {
    asm("fma.rn.f32x2 %0,%1,%2,%0;" : "+l"(d) : "l"(a), "l"(b));
}
__device__ __forceinline__ float sigf(float x) { return 1.f / (1.f + expf(-x)); }

// ---------- relu layer: this thread = column c, rows [hb, hb+12) (6 pairs) ----------
__device__ __forceinline__ void gemm_half(const float* Zin, float* Zout,
                                          const float* __restrict__ W,
                                          const float* __restrict__ bias,
                                          int c, int hb)
{
    ull acc[6];
#pragma unroll
    for (int p = 0; p < 6; p++) acc[p] = 0ull;

#pragma unroll 1
    for (int k0 = 0; k0 < 96; k0 += 8) {
        float w[8];
#pragma unroll
        for (int u = 0; u < 8; u++) w[u] = __ldg(W + (k0 + u) * 96 + c);
#pragma unroll
        for (int u = 0; u < 8; u++) {
            ull w2 = pack2(w[u], w[u]);
            const ulonglong2* zp = (const ulonglong2*)(Zin + (k0 + u) * RS + hb);
            ulonglong2 z0 = zp[0], z1 = zp[1], z2 = zp[2];
            fma2(acc[0], z0.x, w2); fma2(acc[1], z0.y, w2);
            fma2(acc[2], z1.x, w2); fma2(acc[3], z1.y, w2);
            fma2(acc[4], z2.x, w2); fma2(acc[5], z2.y, w2);
        }
    }
    float bv = __ldg(bias + c);
    ull* op = (ull*)(Zout + c * RS + hb);
#pragma unroll
    for (int p = 0; p < 6; p++) {
        float x, y; unpack2(acc[p], x, y);
        x = fmaxf(x + bv, 0.f); y = fmaxf(y + bv, 0.f);
        op[p] = pack2(x, y);
    }
}

// last msg layer: partial row-sum into spart (bias handled at combine)
__device__ __forceinline__ void gemm_half_sum(const float* Zin, float* spart,
                                              const float* __restrict__ W,
                                              int c, int hb, int h, int tid)
{
    ull acc[6];
#pragma unroll
    for (int p = 0; p < 6; p++) acc[p] = 0ull;

#pragma unroll 1
    for (int k0 = 0; k0 < 96; k0 += 8) {
        float w[8];
#pragma unroll
        for (int u = 0; u < 8; u++) w[u] = __ldg(W + (k0 + u) * 96 + c);
#pragma unroll
        for (int u = 0; u < 8; u++) {
            ull w2 = pack2(w[u], w[u]);
            const ulonglong2* zp = (const ulonglong2*)(Zin + (k0 + u) * RS + hb);
            ulonglong2 z0 = zp[0], z1 = zp[1], z2 = zp[2];
            fma2(acc[0], z0.x, w2); fma2(acc[1], z0.y, w2);
            fma2(acc[2], z1.x, w2); fma2(acc[3], z1.y, w2);
            fma2(acc[4], z2.x, w2); fma2(acc[5], z2.y, w2);
        }
    }
    float s = 0.f;
    if (h == 0) {       // rows 0..11, all real
#pragma unroll
        for (int p = 0; p < 6; p++) { float x, y; unpack2(acc[p], x, y); s += x + y; }
    } else {            // rows 12..23: real 12..16 only
        float x, y;
        unpack2(acc[0], x, y); s += x + y;   // rows 12,13
        unpack2(acc[1], x, y); s += x + y;   // rows 14,15
        unpack2(acc[2], x, y); s += x;       // row 16 (17 pad)
    }
    spart[tid] = s;
}

// ---------- fused per-step kernel: CTA == node, 192 threads ----------
__global__ void __launch_bounds__(192, 7) step_kernel(
    int step,
    const int* __restrict__ edges, const int* __restrict__ target,
    const float* __restrict__ msg0_W, const float* __restrict__ msg0_b,
    const float* __restrict__ msg_Ws, const float* __restrict__ msg_bs,
    const float* __restrict__ W_ih, const float* __restrict__ W_hh,
    const float* __restrict__ pred_W, const float* __restrict__ pred_b,
    float* __restrict__ d_out)
{
    __shared__ float ZTa[96 * RS];
    __shared__ float ZTb[96 * RS];
    __shared__ float msg_s[96];
    __shared__ float gate_s[384];
    __shared__ float h2_s[96];
    __shared__ float sQ[96];
    __shared__ float spart[192];
    __shared__ int   sedge[17];

    const int tid = threadIdx.x;
    const int c = tid % 96;          // column
    const int h = tid / 96;          // row-half
    const int hb = h * 12;           // first row of this half
    const int n = blockIdx.x;
    const int j = n & 63;

    const float* Pin  = g_P[step & 1];
    float*       Pout = g_P[(step + 1) & 1];

    if (tid < 17) sedge[tid] = (n & ~63) + __ldg(edges + j * 17 + tid);
    if (tid < 96) sQ[tid] = g_Q[n * 96 + tid];
    __syncthreads();

    // ---- Z0 = relu(P[edge] + Q[self]) into ZTa[c*RS + r]; rows h, h+2, ... ----
    {
        float q = sQ[c];
        for (int r = h; r < 17; r += 2)
            ZTa[c * RS + r] = fmaxf(__ldg(Pin + sedge[r] * 96 + c) + q, 0.f);
        if (h == 1) {
#pragma unroll
            for (int r = 17; r < 24; r++) ZTa[c * RS + r] = 0.f;
        }
    }
    __syncthreads();

    // ---- 3 message layers ----
    gemm_half(ZTa, ZTb, msg_Ws,        msg_bs,      c, hb); __syncthreads();
    gemm_half(ZTb, ZTa, msg_Ws + 9216, msg_bs + 96, c, hb); __syncthreads();
    gemm_half_sum(ZTa, spart, msg_Ws + 18432, c, hb, h, tid); __syncthreads();
    if (tid < 96)
        msg_s[tid] = spart[tid] + spart[96 + tid] + 17.f * __ldg(msg_bs + 192 + tid);
    __syncthreads();

    // ---- gates: pair pi = tid (192 pairs over 192 threads) ----
    {
        int pi = tid;
        ull acc = 0ull;
#pragma unroll 1
        for (int k0 = 0; k0 < 96; k0 += 8) {
            ull wreg[8];
#pragma unroll
            for (int u = 0; u < 8; u++)
                wreg[u] = __ldg((const ull*)(W_ih + (k0 + u) * 384 + 2 * pi));
#pragma unroll
            for (int u = 0; u < 8; u++) {
                float mk = msg_s[k0 + u];
                fma2(acc, pack2(mk, mk), wreg[u]);
            }
        }
        float x, y; unpack2(acc, x, y);
        gate_s[2 * pi]     = x + __ldg(g_Xc + n * 384 + 2 * pi)     + g_Ghh[n * 384 + 2 * pi];
        gate_s[2 * pi + 1] = y + __ldg(g_Xc + n * 384 + 2 * pi + 1) + g_Ghh[n * 384 + 2 * pi + 1];
    }
    __syncthreads();

    // ---- LSTM (dims 0..95 on low threads) ----
    if (tid < 96) {
        float gi = gate_s[tid], gf = gate_s[96 + tid], gg = gate_s[192 + tid], go = gate_s[288 + tid];
        float sp = g_s[n * 96 + tid];
        float s2 = sigf(gf) * sp + sigf(gi) * tanhf(gg);
        float h2 = sigf(go) * tanhf(s2);
        g_s[n * 96 + tid] = s2;
        h2_s[tid] = h2;
    }
    __syncthreads();

    // ---- tail dots for next step: Ghh (all threads), P/Q (high threads) ----
    if (step < NSTEP - 1) {
        {   // Ghh pair tid
            int pi = tid;
            ull acc = 0ull;
#pragma unroll 1
            for (int k0 = 0; k0 < 96; k0 += 8) {
                ull wreg[8];
#pragma unroll
                for (int u = 0; u < 8; u++)
                    wreg[u] = __ldg((const ull*)(W_hh + (k0 + u) * 384 + 2 * pi));
#pragma unroll
                for (int u = 0; u < 8; u++) {
                    float hk = h2_s[k0 + u];
                    fma2(acc, pack2(hk, hk), wreg[u]);
                }
            }
            *(ull*)(g_Ghh + n * 384 + 2 * pi) = acc;
        }
        if (tid >= 96) {   // P pairs 0..47 on 96..143, Q pairs 0..47 on 144..191
            int t = tid - 96;
            int isQ = (t >= 48);
            int pi = isQ ? (t - 48) : t;
            const float* Wp = msg0_W + (isQ ? 96 * 96 : 0);
            ull acc = 0ull;
#pragma unroll 1
            for (int k0 = 0; k0 < 96; k0 += 8) {
                ull wreg[8];
#pragma unroll
                for (int u = 0; u < 8; u++)
                    wreg[u] = __ldg((const ull*)(Wp + (k0 + u) * 96 + 2 * pi));
#pragma unroll
                for (int u = 0; u < 8; u++) {
                    float hk = h2_s[k0 + u];
                    fma2(acc, pack2(hk, hk), wreg[u]);
                }
            }
            if (isQ) {
                float x, y; unpack2(acc, x, y);
                x += __ldg(msg0_b + 2 * pi);
                y += __ldg(msg0_b + 2 * pi + 1);
                *(ull*)(g_Q + n * 96 + 2 * pi) = pack2(x, y);
            } else {
                *(ull*)(Pout + n * 96 + 2 * pi) = acc;
            }
        }
    }

    // ---- prediction head (lanes 0..7 of warp 0) ----
    if (tid < 8) {
        float logit = __ldg(pred_b + tid);
#pragma unroll 8
        for (int k = 0; k < 96; k++)
            logit = fmaf(h2_s[k], __ldg(pred_W + k * 8 + tid), logit);
        const unsigned msk = 0xFFu;
        float m = logit;
        for (int off = 4; off; off >>= 1) m = fmaxf(m, __shfl_xor_sync(msk, m, off));
        float se = expf(logit - m);
        for (int off = 4; off; off >>= 1) se += __shfl_xor_sync(msk, se, off);
        float lse = m + logf(se);
        float bl = logit; int bc = tid;
        for (int off = 4; off; off >>= 1) {
            float ol = __shfl_xor_sync(msk, bl, off);
            int   oc = __shfl_xor_sync(msk, bc, off);
            if (ol > bl || (ol == bl && oc < bc)) { bl = ol; bc = oc; }
        }
        int tgt = __ldg(target + n) - 1;
        if (tid == tgt) g_nodeloss[step * 1024 + n] = lse - logit;
        if (tid == 0) {
            g_nodeok[step * 1024 + n] = (bc == tgt) ? 1 : 0;
            if (step == NSTEP - 1) d_out[33 + n] = (float)bc;
        }
    }
}

// ---------- prologue: feat -> xin MLP -> Xc; init P/Q/Ghh/s ----------
__global__ void __launch_bounds__(128) prologue_kernel(
    const int* __restrict__ x,
    const float* __restrict__ digit_emb, const float* __restrict__ row_emb,
    const float* __restrict__ col_emb,
    const float* __restrict__ in0_W, const float* __restrict__ in0_b,
    const float* __restrict__ in_Ws, const float* __restrict__ in_bs,
    const float* __restrict__ W_ih, const float* __restrict__ b_ih,
    const float* __restrict__ b_hh, const float* __restrict__ msg0_b)
{
    __shared__ float feat[4][48], va[4][96], vb[4][96];
    int tid = threadIdx.x, lane = tid & 31, w = tid >> 5;
    int n = blockIdx.x * 4 + w;
    int j = n & 63;

    if (lane < 16) {
        int xv = x[n];
        feat[w][lane]      = digit_emb[xv * 16 + lane];
        feat[w][16 + lane] = row_emb[(j >> 3) * 16 + lane];
        feat[w][32 + lane] = col_emb[(j & 7) * 16 + lane];
    }
    __syncwarp();

#pragma unroll
    for (int a = 0; a < 3; a++) {
        int cc = lane + 32 * a;
        float acc = in0_b[cc];
        for (int k = 0; k < 48; k++) acc = fmaf(feat[w][k], in0_W[k * 96 + cc], acc);
        va[w][cc] = fmaxf(acc, 0.f);
    }
    __syncwarp();

    for (int l = 0; l < 3; l++) {
        const float* Wl = in_Ws + l * 9216;
        const float* bl = in_bs + l * 96;
        float* src = (l == 1) ? vb[w] : va[w];
        float* dst = (l == 1) ? va[w] : vb[w];
#pragma unroll
        for (int a = 0; a < 3; a++) {
            int cc = lane + 32 * a;
            float acc = bl[cc];
            for (int k = 0; k < 96; k++) acc = fmaf(src[k], Wl[k * 96 + cc], acc);
            dst[cc] = (l < 2) ? fmaxf(acc, 0.f) : acc;
        }
        __syncwarp();
    }

    for (int pi = lane; pi < 192; pi += 32) {
        ull acc = 0ull;
#pragma unroll 4
        for (int k = 0; k < 96; k++) {
            ull w2 = __ldg((const ull*)(W_ih + (96 + k) * 384 + 2 * pi));
            float xk = vb[w][k];
            fma2(acc, pack2(xk, xk), w2);
        }
        float xx, yy; unpack2(acc, xx, yy);
        g_Xc[n * 384 + 2 * pi]     = xx + b_ih[2 * pi]     + b_hh[2 * pi];
        g_Xc[n * 384 + 2 * pi + 1] = yy + b_ih[2 * pi + 1] + b_hh[2 * pi + 1];
    }

    for (int t = lane; t < 96; t += 32) {
        g_P[0][n * 96 + t] = 0.f;
        g_Q[n * 96 + t]    = msg0_b[t];
        g_s[n * 96 + t]    = 0.f;
    }
    for (int t = lane; t < 384; t += 32) g_Ghh[n * 384 + t] = 0.f;
}

// ---------- epilogue ----------
__global__ void __launch_bounds__(512) epilogue_kernel(float* __restrict__ d_out)
{
    __shared__ int   cnt[32];
    __shared__ float red[512];
    int tid = threadIdx.x;
    if (tid < 32) cnt[tid] = 0;
    __syncthreads();

    int s = tid >> 4, b = tid & 15;
    int ok = 1;
    for (int jj = 0; jj < 64; jj++) ok &= g_nodeok[s * 1024 + b * 64 + jj];
    atomicAdd(&cnt[s], ok);

    float ls = 0.f;
    for (int i = tid; i < NSTEP * 1024; i += 512) ls += g_nodeloss[i];
    red[tid] = ls;
    __syncthreads();
    for (int off = 256; off; off >>= 1) {
        if (tid < off) red[tid] += red[tid + off];
        __syncthreads();
    }
    if (tid == 0)  d_out[0] = red[0] / (1024.f * 32.f);
    if (tid < 32)  d_out[1 + tid] = cnt[tid] * (1.f / 16.f);
}

// ---------- launch ----------
extern "C" void kernel_launch(void* const* d_in, const int* in_sizes, int n_in,
                              void* d_out, int out_size)
{
    (void)in_sizes; (void)n_in; (void)out_size;
    const int*   x         = (const int*)  d_in[0];
    const int*   target    = (const int*)  d_in[1];
    const int*   edges     = (const int*)  d_in[2];
    const float* digit_emb = (const float*)d_in[3];
    const float* row_emb   = (const float*)d_in[4];
    const float* col_emb   = (const float*)d_in[5];
    const float* in0_W     = (const float*)d_in[6];
    const float* in0_b     = (const float*)d_in[7];
    const float* in_Ws     = (const float*)d_in[8];
    const float* in_bs     = (const float*)d_in[9];
    const float* msg0_W    = (const float*)d_in[10];
    const float* msg0_b    = (const float*)d_in[11];
    const float* msg_Ws    = (const float*)d_in[12];
    const float* msg_bs    = (const float*)d_in[13];
    const float* W_ih      = (const float*)d_in[14];
    const float* W_hh      = (const float*)d_in[15];
    const float* b_ih      = (const float*)d_in[16];
    const float* b_hh      = (const float*)d_in[17];
    const float* pred_W    = (const float*)d_in[18];
    const float* pred_b    = (const float*)d_in[19];
    float* out = (float*)d_out;

    prologue_kernel<<<256, 128>>>(x, digit_emb, row_emb, col_emb,
                                  in0_W, in0_b, in_Ws, in_bs,
                                  W_ih, b_ih, b_hh, msg0_b);
    for (int s = 0; s < NSTEP; s++)
        step_kernel<<<1024, 192>>>(s, edges, target,
                                   msg0_W, msg0_b, msg_Ws, msg_bs,
                                   W_ih, W_hh, pred_W, pred_b, out);
    epilogue_kernel<<<1, 512>>>(out);
}

// round 6
// speedup vs baseline: 1.0883x; 1.0883x over previous
#include <cuda_runtime.h>
#include <math.h>

// RRN sudoku. B=16, N=64, DEG=17, H=96, 32 steps.
// Round 6: CTA = 8 nodes, 256 threads, register-blocked GEMM (9x6 tile/thread),
// k-paired fma.rn.f32x2, weights staged transposed in smem, 1 CTA/SM.

#define NSTEP 32
typedef unsigned long long ull;

#define MSTR 100     // A tile row stride (floats), rows = [m][k]
#define WSTR 98      // staged weight stride, [c][k]

// smem float offsets
#define O_A     0        // 144*100 = 14400
#define O_W     14400    // 96*98   = 9408
#define O_MSGD  23808    // 960 ull = 1920 fl (16B aligned: 23808*4 % 16 == 0)
#define O_H2D   25728    // 1920
#define O_GATE  27648    // 8*384 = 3072
#define O_H2    30720    // 8*96  = 768
#define O_SEDGE 31488    // 8*17 ints
#define SMEM_FLOATS (31488 + 136)
#define SMEM_BYTES  (SMEM_FLOATS * 4)

// ---------- device scratch (allocation-free) ----------
__device__ float g_P[2][1024 * 96];
__device__ float g_Q[1024 * 96];
__device__ float g_Ghh[1024 * 384];
__device__ float g_Xc[1024 * 384];
__device__ float g_s[1024 * 96];
__device__ float g_nodeloss[NSTEP * 1024];
__device__ int   g_nodeok[NSTEP * 1024];

// ---------- packed f32x2 helpers ----------
__device__ __forceinline__ ull pack2(float x, float y) {
    ull r; asm("mov.b64 %0,{%1,%2};" : "=l"(r) : "f"(x), "f"(y)); return r;
}
__device__ __forceinline__ void unpack2(ull v, float& x, float& y) {
    asm("mov.b64 {%0,%1},%2;" : "=f"(x), "=f"(y) : "l"(v));
}
__device__ __forceinline__ void fma2(ull& d, ull a, ull b) {
    asm("fma.rn.f32x2 %0,%1,%2,%0;" : "+l"(d) : "l"(a), "l"(b));
}
__device__ __forceinline__ float sigf(float x) { return 1.f / (1.f + expf(-x)); }

// ---------- 144x96 @ 96x96 mainloop: thread tile 9 rows x 6 cols, k-paired ----------
__device__ __forceinline__ void kloop54(const float* A, const float* Ws,
                                        ull* acc, int r0, int tx)
{
#pragma unroll
    for (int p = 0; p < 54; p++) acc[p] = 0ull;
#pragma unroll 1
    for (int k0 = 0; k0 < 96; k0 += 2) {
        ull a[9], b[6];
#pragma unroll
        for (int i = 0; i < 6; i++)
            b[i] = *(const ull*)(Ws + (tx + 16 * i) * WSTR + k0);
#pragma unroll
        for (int r = 0; r < 9; r++)
            a[r] = *(const ull*)(A + (r0 + r) * MSTR + k0);
#pragma unroll
        for (int r = 0; r < 9; r++)
#pragma unroll
            for (int i = 0; i < 6; i++)
                fma2(acc[r * 6 + i], a[r], b[i]);
    }
}

__device__ __forceinline__ void stage_w(float* Ws, const float* __restrict__ Wg, int tid)
{
#pragma unroll 4
    for (int e = tid; e < 9216; e += 256) {
        int k = e / 96, c = e - 96 * k;
        Ws[c * WSTR + k] = __ldg(Wg + e);
    }
}

// ---------- fused per-step kernel: CTA = 8 nodes, 256 threads ----------
__global__ void __launch_bounds__(256, 1) step_kernel(
    int step,
    const int* __restrict__ edges, const int* __restrict__ target,
    const float* __restrict__ msg0_W, const float* __restrict__ msg0_b,
    const float* __restrict__ msg_Ws, const float* __restrict__ msg_bs,
    const float* __restrict__ W_ih, const float* __restrict__ W_hh,
    const float* __restrict__ pred_W, const float* __restrict__ pred_b,
    float* __restrict__ d_out)
{
    extern __shared__ float sm[];
    float* A      = sm + O_A;
    float* Ws     = sm + O_W;
    ull*   msgd   = (ull*)(sm + O_MSGD);
    ull*   h2d    = (ull*)(sm + O_H2D);
    float* gate_s = sm + O_GATE;
    float* h2_s   = sm + O_H2;
    int*   sedge  = (int*)(sm + O_SEDGE);

    const int tid  = threadIdx.x;
    const int lane = tid & 31;
    const int w    = tid >> 5;      // warp = node-in-CTA
    const int tx   = tid & 15;
    const int ty   = tid >> 4;
    const int r0   = ty * 9;
    const int n0   = blockIdx.x * 8;

    const float* Pin  = g_P[step & 1];
    float*       Pout = g_P[(step + 1) & 1];

    // ---- gather Z0 = relu(P[edge] + Q[self]) into A[m][k]; stage W layer0 ----
    {
        int n = n0 + w, j = n & 63, base = n0 & ~63;
        if (lane < 17) sedge[w * 17 + lane] = base + __ldg(edges + j * 17 + lane);
        __syncwarp();
        float q0 = g_Q[n * 96 + lane];
        float q1 = g_Q[n * 96 + lane + 32];
        float q2 = g_Q[n * 96 + lane + 64];
#pragma unroll
        for (int r = 0; r < 17; r++) {
            const float* pr = Pin + sedge[w * 17 + r] * 96;
            float v0 = __ldg(pr + lane), v1 = __ldg(pr + lane + 32), v2 = __ldg(pr + lane + 64);
            float* ar = A + (w * 18 + r) * MSTR;
            ar[lane]      = fmaxf(v0 + q0, 0.f);
            ar[lane + 32] = fmaxf(v1 + q1, 0.f);
            ar[lane + 64] = fmaxf(v2 + q2, 0.f);
        }
        float* ap = A + (w * 18 + 17) * MSTR;   // pad row
        ap[lane] = 0.f; ap[lane + 32] = 0.f; ap[lane + 64] = 0.f;
    }
    stage_w(Ws, msg_Ws, tid);
    __syncthreads();

    // ---- layers 0,1 (relu) ----
#pragma unroll 1
    for (int L = 0; L < 2; L++) {
        ull acc[54];
        kloop54(A, Ws, acc, r0, tx);
        __syncthreads();
        float bv[6];
#pragma unroll
        for (int i = 0; i < 6; i++) bv[i] = __ldg(msg_bs + L * 96 + tx + 16 * i);
#pragma unroll
        for (int r = 0; r < 9; r++)
#pragma unroll
            for (int i = 0; i < 6; i++) {
                float x, y; unpack2(acc[r * 6 + i], x, y);
                A[(r0 + r) * MSTR + tx + 16 * i] = fmaxf(x + y + bv[i], 0.f);
            }
        stage_w(Ws, msg_Ws + (L + 1) * 9216, tid);
        __syncthreads();
    }

    // ---- layer 2: no relu, per-node row sum -> msgd (duplicated pairs [k][node]) ----
    {
        ull acc[54];
        kloop54(A, Ws, acc, r0, tx);
        float t[6];
#pragma unroll
        for (int i = 0; i < 6; i++) t[i] = 0.f;
#pragma unroll
        for (int r = 0; r < 9; r++) {
            bool real = (r < 8) || ((ty & 1) == 0);   // odd ty local row 8 = pad
#pragma unroll
            for (int i = 0; i < 6; i++) {
                float x, y; unpack2(acc[r * 6 + i], x, y);
                if (real) t[i] += x + y;
            }
        }
#pragma unroll
        for (int i = 0; i < 6; i++) {
            float o = __shfl_down_sync(0xffffffffu, t[i], 16);
            if (lane < 16) {
                int c = tx + 16 * i;
                float m = t[i] + o + 17.f * __ldg(msg_bs + 192 + c);
                msgd[c * 10 + w] = pack2(m, m);
            }
        }
    }
    __syncthreads();

    // ---- gates: thread = col-pair p (<192), acc over 8 nodes ----
    if (tid < 192) {
        const int p = tid;
        ull acc2[8];
#pragma unroll
        for (int nd = 0; nd < 8; nd++) acc2[nd] = 0ull;
#pragma unroll 2
        for (int k = 0; k < 96; k++) {
            ull wp = __ldg((const ull*)(W_ih + k * 384 + 2 * p));
            ulonglong2 m01 = *(const ulonglong2*)(msgd + k * 10 + 0);
            ulonglong2 m23 = *(const ulonglong2*)(msgd + k * 10 + 2);
            ulonglong2 m45 = *(const ulonglong2*)(msgd + k * 10 + 4);
            ulonglong2 m67 = *(const ulonglong2*)(msgd + k * 10 + 6);
            fma2(acc2[0], m01.x, wp); fma2(acc2[1], m01.y, wp);
            fma2(acc2[2], m23.x, wp); fma2(acc2[3], m23.y, wp);
            fma2(acc2[4], m45.x, wp); fma2(acc2[5], m45.y, wp);
            fma2(acc2[6], m67.x, wp); fma2(acc2[7], m67.y, wp);
        }
#pragma unroll
        for (int nd = 0; nd < 8; nd++) {
            int n = n0 + nd;
            float x, y; unpack2(acc2[nd], x, y);
            float2 xc = *(const float2*)(g_Xc  + n * 384 + 2 * p);
            float2 gh = *(const float2*)(g_Ghh + n * 384 + 2 * p);
            gate_s[nd * 384 + 2 * p]     = x + xc.x + gh.x;
            gate_s[nd * 384 + 2 * p + 1] = y + xc.y + gh.y;
        }
    }
    __syncthreads();

    // ---- LSTM: 768 (node,dim) over 256 threads ----
#pragma unroll
    for (int q = 0; q < 3; q++) {
        int idx = tid + 256 * q;
        int nd = idx / 96, dim = idx - 96 * nd;
        int n = n0 + nd;
        float gi = gate_s[nd * 384 + dim];
        float gf = gate_s[nd * 384 + 96 + dim];
        float gg = gate_s[nd * 384 + 192 + dim];
        float go = gate_s[nd * 384 + 288 + dim];
        float sp = g_s[n * 96 + dim];
        float s2 = sigf(gf) * sp + sigf(gi) * tanhf(gg);
        float h2 = sigf(go) * tanhf(s2);
        g_s[n * 96 + dim] = s2;
        h2_s[nd * 96 + dim] = h2;
        h2d[dim * 10 + nd] = pack2(h2, h2);
    }
    __syncthreads();

    // ---- phase2: Ghh (192 pairs) + P (48) + Q (48) for next step ----
    if (step < NSTEP - 1) {
        for (int jj = tid; jj < 288; jj += 256) {
            const float* Wp; int ldw, cp; float bx = 0.f, by = 0.f;
            float* dst; int dstride;
            if (jj < 192)      { Wp = W_hh;             ldw = 384; cp = jj;       dst = g_Ghh; dstride = 384; }
            else if (jj < 240) { Wp = msg0_W;           ldw = 96;  cp = jj - 192; dst = Pout;  dstride = 96; }
            else               { Wp = msg0_W + 96 * 96; ldw = 96;  cp = jj - 240; dst = g_Q;   dstride = 96;
                                 bx = __ldg(msg0_b + 2 * cp); by = __ldg(msg0_b + 2 * cp + 1); }
            ull acc2[8];
#pragma unroll
            for (int nd = 0; nd < 8; nd++) acc2[nd] = 0ull;
#pragma unroll 2
            for (int k = 0; k < 96; k++) {
                ull wp = __ldg((const ull*)(Wp + k * ldw + 2 * cp));
                ulonglong2 h01 = *(const ulonglong2*)(h2d + k * 10 + 0);
                ulonglong2 h23 = *(const ulonglong2*)(h2d + k * 10 + 2);
                ulonglong2 h45 = *(const ulonglong2*)(h2d + k * 10 + 4);
                ulonglong2 h67 = *(const ulonglong2*)(h2d + k * 10 + 6);
                fma2(acc2[0], h01.x, wp); fma2(acc2[1], h01.y, wp);
                fma2(acc2[2], h23.x, wp); fma2(acc2[3], h23.y, wp);
                fma2(acc2[4], h45.x, wp); fma2(acc2[5], h45.y, wp);
                fma2(acc2[6], h67.x, wp); fma2(acc2[7], h67.y, wp);
            }
#pragma unroll
            for (int nd = 0; nd < 8; nd++) {
                float x, y; unpack2(acc2[nd], x, y);
                *(float2*)(dst + (n0 + nd) * dstride + 2 * cp) = make_float2(x + bx, y + by);
            }
        }
    }

    // ---- prediction head: warp w = node w, lanes 0..7 ----
    {
        int n = n0 + w;
        if (lane < 8) {
            float logit = __ldg(pred_b + lane);
            const float* hr = h2_s + w * 96;
#pragma unroll 8
            for (int k = 0; k < 96; k++)
                logit = fmaf(hr[k], __ldg(pred_W + k * 8 + lane), logit);
            const unsigned msk = 0xFFu;
            float mx = logit;
            for (int off = 4; off; off >>= 1) mx = fmaxf(mx, __shfl_xor_sync(msk, mx, off));
            float se = expf(logit - mx);
            for (int off = 4; off; off >>= 1) se += __shfl_xor_sync(msk, se, off);
            float lse = mx + logf(se);
            float bl = logit; int bc = lane;
            for (int off = 4; off; off >>= 1) {
                float ol = __shfl_xor_sync(msk, bl, off);
                int   oc = __shfl_xor_sync(msk, bc, off);
                if (ol > bl || (ol == bl && oc < bc)) { bl = ol; bc = oc; }
            }
            int tgt = __ldg(target + n) - 1;
            if (lane == tgt) g_nodeloss[step * 1024 + n] = lse - logit;
            if (lane == 0) {
                g_nodeok[step * 1024 + n] = (bc == tgt) ? 1 : 0;
                if (step == NSTEP - 1) d_out[33 + n] = (float)bc;
            }
        }
    }
}

// ---------- prologue: feat -> xin MLP -> Xc; init P/Q/Ghh/s ----------
__global__ void __launch_bounds__(128) prologue_kernel(
    const int* __restrict__ x,
    const float* __restrict__ digit_emb, const float* __restrict__ row_emb,
    const float* __restrict__ col_emb,
    const float* __restrict__ in0_W, const float* __restrict__ in0_b,
    const float* __restrict__ in_Ws, const float* __restrict__ in_bs,
    const float* __restrict__ W_ih, const float* __restrict__ b_ih,
    const float* __restrict__ b_hh, const float* __restrict__ msg0_b)
{
    __shared__ float feat[4][48], va[4][96], vb[4][96];
    int tid = threadIdx.x, lane = tid & 31, w = tid >> 5;
    int n = blockIdx.x * 4 + w;
    int j = n & 63;

    if (lane < 16) {
        int xv = x[n];
        feat[w][lane]      = digit_emb[xv * 16 + lane];
        feat[w][16 + lane] = row_emb[(j >> 3) * 16 + lane];
        feat[w][32 + lane] = col_emb[(j & 7) * 16 + lane];
    }
    __syncwarp();

#pragma unroll
    for (int a = 0; a < 3; a++) {
        int cc = lane + 32 * a;
        float acc = in0_b[cc];
        for (int k = 0; k < 48; k++) acc = fmaf(feat[w][k], in0_W[k * 96 + cc], acc);
        va[w][cc] = fmaxf(acc, 0.f);
    }
    __syncwarp();

    for (int l = 0; l < 3; l++) {
        const float* Wl = in_Ws + l * 9216;
        const float* bl = in_bs + l * 96;
        float* src = (l == 1) ? vb[w] : va[w];
        float* dst = (l == 1) ? va[w] : vb[w];
#pragma unroll
        for (int a = 0; a < 3; a++) {
            int cc = lane + 32 * a;
            float acc = bl[cc];
            for (int k = 0; k < 96; k++) acc = fmaf(src[k], Wl[k * 96 + cc], acc);
            dst[cc] = (l < 2) ? fmaxf(acc, 0.f) : acc;
        }
        __syncwarp();
    }

    for (int pi = lane; pi < 192; pi += 32) {
        ull acc = 0ull;
#pragma unroll 4
        for (int k = 0; k < 96; k++) {
            ull w2 = __ldg((const ull*)(W_ih + (96 + k) * 384 + 2 * pi));
            float xk = vb[w][k];
            fma2(acc, pack2(xk, xk), w2);
        }
        float xx, yy; unpack2(acc, xx, yy);
        g_Xc[n * 384 + 2 * pi]     = xx + b_ih[2 * pi]     + b_hh[2 * pi];
        g_Xc[n * 384 + 2 * pi + 1] = yy + b_ih[2 * pi + 1] + b_hh[2 * pi + 1];
    }

    for (int t = lane; t < 96; t += 32) {
        g_P[0][n * 96 + t] = 0.f;
        g_Q[n * 96 + t]    = msg0_b[t];
        g_s[n * 96 + t]    = 0.f;
    }
    for (int t = lane; t < 384; t += 32) g_Ghh[n * 384 + t] = 0.f;
}

// ---------- epilogue ----------
__global__ void __launch_bounds__(512) epilogue_kernel(float* __restrict__ d_out)
{
    __shared__ int   cnt[32];
    __shared__ float red[512];
    int tid = threadIdx.x;
    if (tid < 32) cnt[tid] = 0;
    __syncthreads();

    int s = tid >> 4, b = tid & 15;
    int ok = 1;
    for (int jj = 0; jj < 64; jj++) ok &= g_nodeok[s * 1024 + b * 64 + jj];
    atomicAdd(&cnt[s], ok);

    float ls = 0.f;
    for (int i = tid; i < NSTEP * 1024; i += 512) ls += g_nodeloss[i];
    red[tid] = ls;
    __syncthreads();
    for (int off = 256; off; off >>= 1) {
        if (tid < off) red[tid] += red[tid + off];
        __syncthreads();
    }
    if (tid == 0)  d_out[0] = red[0] / (1024.f * 32.f);
    if (tid < 32)  d_out[1 + tid] = cnt[tid] * (1.f / 16.f);
}

// ---------- launch ----------
extern "C" void kernel_launch(void* const* d_in, const int* in_sizes, int n_in,
                              void* d_out, int out_size)
{
    (void)in_sizes; (void)n_in; (void)out_size;
    const int*   x         = (const int*)  d_in[0];
    const int*   target    = (const int*)  d_in[1];
    const int*   edges     = (const int*)  d_in[2];
    const float* digit_emb = (const float*)d_in[3];
    const float* row_emb   = (const float*)d_in[4];
    const float* col_emb   = (const float*)d_in[5];
    const float* in0_W     = (const float*)d_in[6];
    const float* in0_b     = (const float*)d_in[7];
    const float* in_Ws     = (const float*)d_in[8];
    const float* in_bs     = (const float*)d_in[9];
    const float* msg0_W    = (const float*)d_in[10];
    const float* msg0_b    = (const float*)d_in[11];
    const float* msg_Ws    = (const float*)d_in[12];
    const float* msg_bs    = (const float*)d_in[13];
    const float* W_ih      = (const float*)d_in[14];
    const float* W_hh      = (const float*)d_in[15];
    const float* b_ih      = (const float*)d_in[16];
    const float* b_hh      = (const float*)d_in[17];
    const float* pred_W    = (const float*)d_in[18];
    const float* pred_b    = (const float*)d_in[19];
    float* out = (float*)d_out;

    cudaFuncSetAttribute(step_kernel, cudaFuncAttributeMaxDynamicSharedMemorySize, SMEM_BYTES);

    prologue_kernel<<<256, 128>>>(x, digit_emb, row_emb, col_emb,
                                  in0_W, in0_b, in_Ws, in_bs,
                                  W_ih, b_ih, b_hh, msg0_b);
    for (int s = 0; s < NSTEP; s++)
        step_kernel<<<128, 256, SMEM_BYTES>>>(s, edges, target,
                                              msg0_W, msg0_b, msg_Ws, msg_bs,
                                              W_ih, W_hh, pred_W, pred_b, out);
    epilogue_kernel<<<1, 512>>>(out);
}

// round 7
// speedup vs baseline: 1.2629x; 1.1604x over previous
#include <cuda_runtime.h>
#include <math.h>

// RRN sudoku. B=16, N=64, DEG=17, H=96, 32 steps.
// Round 7: fused step kernel, CTA = 2 nodes x 96 threads, grid 512.
// Mainloop: thread = 3 cols x 6 row-pairs, broadcast LDS.128 Z loads (RS=44).
// Tails: 2-node register blocking with duplicated-pair smem operands.

#define NSTEP 32
#define RS 44
typedef unsigned long long ull;

// ---------- device scratch (allocation-free) ----------
__device__ float g_P[2][1024 * 96];
__device__ float g_Q[1024 * 96];
__device__ float g_Ghh[1024 * 384];
__device__ float g_Xc[1024 * 384];
__device__ float g_s[1024 * 96];
__device__ float g_nodeloss[NSTEP * 1024];
__device__ int   g_nodeok[NSTEP * 1024];

// ---------- packed f32x2 helpers ----------
__device__ __forceinline__ ull pack2(float x, float y) {
    ull r; asm("mov.b64 %0,{%1,%2};" : "=l"(r) : "f"(x), "f"(y)); return r;
}
__device__ __forceinline__ void unpack2(ull v, float& x, float& y) {
    asm("mov.b64 {%0,%1},%2;" : "=f"(x), "=f"(y) : "l"(v));
}
__device__ __forceinline__ void fma2(ull& d, ull a, ull b) {
    asm("fma.rn.f32x2 %0,%1,%2,%0;" : "+l"(d) : "l"(a), "l"(b));
}
__device__ __forceinline__ float sigf(float x) { return 1.f / (1.f + expf(-x)); }

// ---------- 36x96 @ 96x96 layer, relu. thread = cols {tx,tx+32,tx+64} x pairs {6ty..6ty+5} ----------
__device__ __forceinline__ void layer_relu(const float* Zin, float* Zout,
                                           const float* __restrict__ Wg,
                                           const float* __restrict__ bias,
                                           int tx, int ty)
{
    ull acc[6][3];
#pragma unroll
    for (int j = 0; j < 6; j++)
#pragma unroll
        for (int i = 0; i < 3; i++) acc[j][i] = 0ull;

    const int rb = 12 * ty;
#pragma unroll 1
    for (int k0 = 0; k0 < 96; k0 += 4) {
        float w[4][3];
#pragma unroll
        for (int u = 0; u < 4; u++)
#pragma unroll
            for (int i = 0; i < 3; i++)
                w[u][i] = __ldg(Wg + (k0 + u) * 96 + tx + 32 * i);
#pragma unroll
        for (int u = 0; u < 4; u++) {
            const float* zrow = Zin + (k0 + u) * RS + rb;
            ulonglong2 zA = *(const ulonglong2*)(zrow);
            ulonglong2 zB = *(const ulonglong2*)(zrow + 4);
            ulonglong2 zC = *(const ulonglong2*)(zrow + 8);
#pragma unroll
            for (int i = 0; i < 3; i++) {
                ull w2 = pack2(w[u][i], w[u][i]);
                fma2(acc[0][i], zA.x, w2); fma2(acc[1][i], zA.y, w2);
                fma2(acc[2][i], zB.x, w2); fma2(acc[3][i], zB.y, w2);
                fma2(acc[4][i], zC.x, w2); fma2(acc[5][i], zC.y, w2);
            }
        }
    }
#pragma unroll
    for (int i = 0; i < 3; i++) {
        int c = tx + 32 * i;
        float bv = __ldg(bias + c);
#pragma unroll
        for (int j = 0; j < 6; j++) {
            float x, y; unpack2(acc[j][i], x, y);
            *(ull*)(Zout + c * RS + 2 * (6 * ty + j)) =
                pack2(fmaxf(x + bv, 0.f), fmaxf(y + bv, 0.f));
        }
    }
}

// last layer: partial per-node row sums -> spart[ty*192 + nd*96 + c]
__device__ __forceinline__ void layer_sum(const float* Zin, float* spart,
                                          const float* __restrict__ Wg,
                                          int tx, int ty)
{
    ull acc[6][3];
#pragma unroll
    for (int j = 0; j < 6; j++)
#pragma unroll
        for (int i = 0; i < 3; i++) acc[j][i] = 0ull;

    const int rb = 12 * ty;
#pragma unroll 1
    for (int k0 = 0; k0 < 96; k0 += 4) {
        float w[4][3];
#pragma unroll
        for (int u = 0; u < 4; u++)
#pragma unroll
            for (int i = 0; i < 3; i++)
                w[u][i] = __ldg(Wg + (k0 + u) * 96 + tx + 32 * i);
#pragma unroll
        for (int u = 0; u < 4; u++) {
            const float* zrow = Zin + (k0 + u) * RS + rb;
            ulonglong2 zA = *(const ulonglong2*)(zrow);
            ulonglong2 zB = *(const ulonglong2*)(zrow + 4);
            ulonglong2 zC = *(const ulonglong2*)(zrow + 8);
#pragma unroll
            for (int i = 0; i < 3; i++) {
                ull w2 = pack2(w[u][i], w[u][i]);
                fma2(acc[0][i], zA.x, w2); fma2(acc[1][i], zA.y, w2);
                fma2(acc[2][i], zB.x, w2); fma2(acc[3][i], zB.y, w2);
                fma2(acc[4][i], zC.x, w2); fma2(acc[5][i], zC.y, w2);
            }
        }
    }
    // pairs owned: p = 6ty+j. node0 = p 0..8 (p8 drop y = pad row17),
    // node1 = p 9..17 (p17 drop y = pad row35).
#pragma unroll
    for (int i = 0; i < 3; i++) {
        int c = tx + 32 * i;
        float s0 = 0.f, s1 = 0.f;
        float x, y;
        if (ty == 0) {
#pragma unroll
            for (int j = 0; j < 6; j++) { unpack2(acc[j][i], x, y); s0 += x + y; }
        } else if (ty == 1) {
            unpack2(acc[0][i], x, y); s0 += x + y;    // p6
            unpack2(acc[1][i], x, y); s0 += x + y;    // p7
            unpack2(acc[2][i], x, y); s0 += x;        // p8 (y = pad)
            unpack2(acc[3][i], x, y); s1 += x + y;    // p9
            unpack2(acc[4][i], x, y); s1 += x + y;    // p10
            unpack2(acc[5][i], x, y); s1 += x + y;    // p11
        } else {
#pragma unroll
            for (int j = 0; j < 5; j++) { unpack2(acc[j][i], x, y); s1 += x + y; }
            unpack2(acc[5][i], x, y); s1 += x;        // p17 (y = pad)
        }
        spart[ty * 192 + c]      = s0;
        spart[ty * 192 + 96 + c] = s1;
    }
}

// ---------- fused per-step kernel: CTA = 2 nodes, 96 threads ----------
__global__ void __launch_bounds__(96, 5) step_kernel(
    int step,
    const int* __restrict__ edges, const int* __restrict__ target,
    const float* __restrict__ msg0_W, const float* __restrict__ msg0_b,
    const float* __restrict__ msg_Ws, const float* __restrict__ msg_bs,
    const float* __restrict__ W_ih, const float* __restrict__ W_hh,
    const float* __restrict__ pred_W, const float* __restrict__ pred_b,
    float* __restrict__ d_out)
{
    __shared__ __align__(16) float ZTa[96 * RS];
    __shared__ __align__(16) float ZTb[96 * RS];
    __shared__ __align__(16) ull   msgd[192];    // [k*2 + nd], duplicated pairs
    __shared__ __align__(16) ull   h2d[192];
    __shared__ float sQ[192];
    __shared__ float spart[576];
    __shared__ float gate_s[768];
    __shared__ float h2_s[192];
    __shared__ int   sedge[34];

    const int tid = threadIdx.x;
    const int tx = tid & 31, ty = tid >> 5;
    const int n0 = blockIdx.x * 2;

    const float* Pin  = g_P[step & 1];
    float*       Pout = g_P[(step + 1) & 1];

    if (tid < 34) {
        int nd = (tid >= 17), r = tid - 17 * nd;
        int j = (n0 + nd) & 63;
        sedge[tid] = (n0 & ~63) + __ldg(edges + j * 17 + r);
    }
    sQ[tid]      = g_Q[n0 * 96 + tid];
    sQ[96 + tid] = g_Q[n0 * 96 + 96 + tid];
    __syncthreads();

    // ---- Z0 = relu(P[edge] + Q[self]); rows 0..17 node0 (17 pad), 18..35 node1 (35 pad) ----
    {
        int c = tid;
        float q0 = sQ[c], q1 = sQ[96 + c];
        float* z = ZTa + c * RS;
#pragma unroll
        for (int r = 0; r < 17; r++)
            z[r] = fmaxf(__ldg(Pin + sedge[r] * 96 + c) + q0, 0.f);
        z[17] = 0.f;
#pragma unroll
        for (int r = 0; r < 17; r++)
            z[18 + r] = fmaxf(__ldg(Pin + sedge[17 + r] * 96 + c) + q1, 0.f);
        z[35] = 0.f;
    }
    __syncthreads();

    // ---- 3 message layers ----
    layer_relu(ZTa, ZTb, msg_Ws,        msg_bs,      tx, ty); __syncthreads();
    layer_relu(ZTb, ZTa, msg_Ws + 9216, msg_bs + 96, tx, ty); __syncthreads();
    layer_sum (ZTa, spart, msg_Ws + 18432, tx, ty);           __syncthreads();

    // combine partials -> msgd (duplicated pairs, both nodes interleaved)
    {
        float bv = 17.f * __ldg(msg_bs + 192 + tid);
        float m0 = spart[tid]       + spart[192 + tid] + spart[384 + tid] + bv;
        float m1 = spart[96 + tid]  + spart[288 + tid] + spart[480 + tid] + bv;
        msgd[tid * 2]     = pack2(m0, m0);
        msgd[tid * 2 + 1] = pack2(m1, m1);
    }
    __syncthreads();

    // ---- gates: 192 pairs x 2 nodes; per k one LDS.128 serves both nodes ----
#pragma unroll
    for (int pass = 0; pass < 2; pass++) {
        int pi = tid + 96 * pass;
        ull a0 = 0ull, a1 = 0ull;
#pragma unroll 1
        for (int k0 = 0; k0 < 96; k0 += 8) {
            ull wp[8];
#pragma unroll
            for (int u = 0; u < 8; u++)
                wp[u] = __ldg((const ull*)(W_ih + (k0 + u) * 384 + 2 * pi));
#pragma unroll
            for (int u = 0; u < 8; u++) {
                ulonglong2 m = *(const ulonglong2*)(msgd + 2 * (k0 + u));
                fma2(a0, m.x, wp[u]);
                fma2(a1, m.y, wp[u]);
            }
        }
        float x0, y0, x1, y1; unpack2(a0, x0, y0); unpack2(a1, x1, y1);
        float2 xc0 = *(const float2*)(g_Xc  + n0 * 384 + 2 * pi);
        float2 gh0 = *(const float2*)(g_Ghh + n0 * 384 + 2 * pi);
        float2 xc1 = *(const float2*)(g_Xc  + (n0 + 1) * 384 + 2 * pi);
        float2 gh1 = *(const float2*)(g_Ghh + (n0 + 1) * 384 + 2 * pi);
        gate_s[2 * pi]           = x0 + xc0.x + gh0.x;
        gate_s[2 * pi + 1]       = y0 + xc0.y + gh0.y;
        gate_s[384 + 2 * pi]     = x1 + xc1.x + gh1.x;
        gate_s[384 + 2 * pi + 1] = y1 + xc1.y + gh1.y;
    }
    __syncthreads();

    // ---- LSTM ----
#pragma unroll
    for (int nd = 0; nd < 2; nd++) {
        int n = n0 + nd, dim = tid;
        float gi = gate_s[nd * 384 + dim];
        float gf = gate_s[nd * 384 + 96 + dim];
        float gg = gate_s[nd * 384 + 192 + dim];
        float go = gate_s[nd * 384 + 288 + dim];
        float sp = g_s[n * 96 + dim];
        float s2 = sigf(gf) * sp + sigf(gi) * tanhf(gg);
        float h2 = sigf(go) * tanhf(s2);
        g_s[n * 96 + dim] = s2;
        h2_s[nd * 96 + dim] = h2;
        h2d[dim * 2 + nd] = pack2(h2, h2);
    }
    __syncthreads();

    // ---- next-step precompute: P / Q (one pass) + Ghh (two passes) ----
    if (step < NSTEP - 1) {
        {
            int isQ = (tid >= 48);
            int cp = isQ ? (tid - 48) : tid;
            const float* Wp = msg0_W + (isQ ? 9216 : 0);
            ull a0 = 0ull, a1 = 0ull;
#pragma unroll 1
            for (int k0 = 0; k0 < 96; k0 += 8) {
                ull wp[8];
#pragma unroll
                for (int u = 0; u < 8; u++)
                    wp[u] = __ldg((const ull*)(Wp + (k0 + u) * 96 + 2 * cp));
#pragma unroll
                for (int u = 0; u < 8; u++) {
                    ulonglong2 h = *(const ulonglong2*)(h2d + 2 * (k0 + u));
                    fma2(a0, h.x, wp[u]);
                    fma2(a1, h.y, wp[u]);
                }
            }
            float x0, y0, x1, y1; unpack2(a0, x0, y0); unpack2(a1, x1, y1);
            if (isQ) {
                float bx = __ldg(msg0_b + 2 * cp), by = __ldg(msg0_b + 2 * cp + 1);
                *(float2*)(g_Q + n0 * 96 + 2 * cp)       = make_float2(x0 + bx, y0 + by);
                *(float2*)(g_Q + (n0 + 1) * 96 + 2 * cp) = make_float2(x1 + bx, y1 + by);
            } else {
                *(float2*)(Pout + n0 * 96 + 2 * cp)       = make_float2(x0, y0);
                *(float2*)(Pout + (n0 + 1) * 96 + 2 * cp) = make_float2(x1, y1);
            }
        }
#pragma unroll
        for (int pass = 0; pass < 2; pass++) {
            int pi = tid + 96 * pass;
            ull a0 = 0ull, a1 = 0ull;
#pragma unroll 1
            for (int k0 = 0; k0 < 96; k0 += 8) {
                ull wp[8];
#pragma unroll
                for (int u = 0; u < 8; u++)
                    wp[u] = __ldg((const ull*)(W_hh + (k0 + u) * 384 + 2 * pi));
#pragma unroll
                for (int u = 0; u < 8; u++) {
                    ulonglong2 h = *(const ulonglong2*)(h2d + 2 * (k0 + u));
                    fma2(a0, h.x, wp[u]);
                    fma2(a1, h.y, wp[u]);
                }
            }
            float x0, y0, x1, y1; unpack2(a0, x0, y0); unpack2(a1, x1, y1);
            *(float2*)(g_Ghh + n0 * 384 + 2 * pi)       = make_float2(x0, y0);
            *(float2*)(g_Ghh + (n0 + 1) * 384 + 2 * pi) = make_float2(x1, y1);
        }
    }

    // ---- prediction head: warp 0 -> node0, warp 1 -> node1 (lanes 0..7) ----
    if (ty < 2 && tx < 8) {
        int n = n0 + ty, d = tx;
        float logit = __ldg(pred_b + d);
        const float* hr = h2_s + ty * 96;
#pragma unroll 8
        for (int k = 0; k < 96; k++)
            logit = fmaf(hr[k], __ldg(pred_W + k * 8 + d), logit);
        const unsigned msk = 0xFFu;
        float mx = logit;
        for (int off = 4; off; off >>= 1) mx = fmaxf(mx, __shfl_xor_sync(msk, mx, off));
        float se = expf(logit - mx);
        for (int off = 4; off; off >>= 1) se += __shfl_xor_sync(msk, se, off);
        float lse = mx + logf(se);
        float bl = logit; int bc = d;
        for (int off = 4; off; off >>= 1) {
            float ol = __shfl_xor_sync(msk, bl, off);
            int   oc = __shfl_xor_sync(msk, bc, off);
            if (ol > bl || (ol == bl && oc < bc)) { bl = ol; bc = oc; }
        }
        int tgt = __ldg(target + n) - 1;
        if (d == tgt) g_nodeloss[step * 1024 + n] = lse - logit;
        if (d == 0) {
            g_nodeok[step * 1024 + n] = (bc == tgt) ? 1 : 0;
            if (step == NSTEP - 1) d_out[33 + n] = (float)bc;
        }
    }
}

// ---------- prologue: feat -> xin MLP -> Xc; init P/Q/Ghh/s ----------
__global__ void __launch_bounds__(128) prologue_kernel(
    const int* __restrict__ x,
    const float* __restrict__ digit_emb, const float* __restrict__ row_emb,
    const float* __restrict__ col_emb,
    const float* __restrict__ in0_W, const float* __restrict__ in0_b,
    const float* __restrict__ in_Ws, const float* __restrict__ in_bs,
    const float* __restrict__ W_ih, const float* __restrict__ b_ih,
    const float* __restrict__ b_hh, const float* __restrict__ msg0_b)
{
    __shared__ float feat[4][48], va[4][96], vb[4][96];
    int tid = threadIdx.x, lane = tid & 31, w = tid >> 5;
    int n = blockIdx.x * 4 + w;
    int j = n & 63;

    if (lane < 16) {
        int xv = x[n];
        feat[w][lane]      = digit_emb[xv * 16 + lane];
        feat[w][16 + lane] = row_emb[(j >> 3) * 16 + lane];
        feat[w][32 + lane] = col_emb[(j & 7) * 16 + lane];
    }
    __syncwarp();

#pragma unroll
    for (int a = 0; a < 3; a++) {
        int cc = lane + 32 * a;
        float acc = in0_b[cc];
        for (int k = 0; k < 48; k++) acc = fmaf(feat[w][k], in0_W[k * 96 + cc], acc);
        va[w][cc] = fmaxf(acc, 0.f);
    }
    __syncwarp();

    for (int l = 0; l < 3; l++) {
        const float* Wl = in_Ws + l * 9216;
        const float* bl = in_bs + l * 96;
        float* src = (l == 1) ? vb[w] : va[w];
        float* dst = (l == 1) ? va[w] : vb[w];
#pragma unroll
        for (int a = 0; a < 3; a++) {
            int cc = lane + 32 * a;
            float acc = bl[cc];
            for (int k = 0; k < 96; k++) acc = fmaf(src[k], Wl[k * 96 + cc], acc);
            dst[cc] = (l < 2) ? fmaxf(acc, 0.f) : acc;
        }
        __syncwarp();
    }

    for (int pi = lane; pi < 192; pi += 32) {
        ull acc = 0ull;
#pragma unroll 4
        for (int k = 0; k < 96; k++) {
            ull w2 = __ldg((const ull*)(W_ih + (96 + k) * 384 + 2 * pi));
            float xk = vb[w][k];
            fma2(acc, pack2(xk, xk), w2);
        }
        float xx, yy; unpack2(acc, xx, yy);
        g_Xc[n * 384 + 2 * pi]     = xx + b_ih[2 * pi]     + b_hh[2 * pi];
        g_Xc[n * 384 + 2 * pi + 1] = yy + b_ih[2 * pi + 1] + b_hh[2 * pi + 1];
    }

    for (int t = lane; t < 96; t += 32) {
        g_P[0][n * 96 + t] = 0.f;
        g_Q[n * 96 + t]    = msg0_b[t];
        g_s[n * 96 + t]    = 0.f;
    }
    for (int t = lane; t < 384; t += 32) g_Ghh[n * 384 + t] = 0.f;
}

// ---------- epilogue ----------
__global__ void __launch_bounds__(512) epilogue_kernel(float* __restrict__ d_out)
{
    __shared__ int   cnt[32];
    __shared__ float red[512];
    int tid = threadIdx.x;
    if (tid < 32) cnt[tid] = 0;
    __syncthreads();

    int s = tid >> 4, b = tid & 15;
    int ok = 1;
    for (int jj = 0; jj < 64; jj++) ok &= g_nodeok[s * 1024 + b * 64 + jj];
    atomicAdd(&cnt[s], ok);

    float ls = 0.f;
    for (int i = tid; i < NSTEP * 1024; i += 512) ls += g_nodeloss[i];
    red[tid] = ls;
    __syncthreads();
    for (int off = 256; off; off >>= 1) {
        if (tid < off) red[tid] += red[tid + off];
        __syncthreads();
    }
    if (tid == 0)  d_out[0] = red[0] / (1024.f * 32.f);
    if (tid < 32)  d_out[1 + tid] = cnt[tid] * (1.f / 16.f);
}

// ---------- launch ----------
extern "C" void kernel_launch(void* const* d_in, const int* in_sizes, int n_in,
                              void* d_out, int out_size)
{
    (void)in_sizes; (void)n_in; (void)out_size;
    const int*   x         = (const int*)  d_in[0];
    const int*   target    = (const int*)  d_in[1];
    const int*   edges     = (const int*)  d_in[2];
    const float* digit_emb = (const float*)d_in[3];
    const float* row_emb   = (const float*)d_in[4];
    const float* col_emb   = (const float*)d_in[5];
    const float* in0_W     = (const float*)d_in[6];
    const float* in0_b     = (const float*)d_in[7];
    const float* in_Ws     = (const float*)d_in[8];
    const float* in_bs     = (const float*)d_in[9];
    const float* msg0_W    = (const float*)d_in[10];
    const float* msg0_b    = (const float*)d_in[11];
    const float* msg_Ws    = (const float*)d_in[12];
    const float* msg_bs    = (const float*)d_in[13];
    const float* W_ih      = (const float*)d_in[14];
    const float* W_hh      = (const float*)d_in[15];
    const float* b_ih      = (const float*)d_in[16];
    const float* b_hh      = (const float*)d_in[17];
    const float* pred_W    = (const float*)d_in[18];
    const float* pred_b    = (const float*)d_in[19];
    float* out = (float*)d_out;

    prologue_kernel<<<256, 128>>>(x, digit_emb, row_emb, col_emb,
                                  in0_W, in0_b, in_Ws, in_bs,
                                  W_ih, b_ih, b_hh, msg0_b);
    for (int s = 0; s < NSTEP; s++)
        step_kernel<<<512, 96>>>(s, edges, target,
                                 msg0_W, msg0_b, msg_Ws, msg_bs,
                                 W_ih, W_hh, pred_W, pred_b, out);
    epilogue_kernel<<<1, 512>>>(out);
}